// round 16
// baseline (speedup 1.0000x reference)
#include <cuda_runtime.h>
#include <cuda_fp16.h>
#include <math.h>
#include <cstdint>

#define NB 4
#define NS 2048
#define ND 768
#define NH 12
#define NDK 64
#define NM (NB*NS)
#define PNKT (ND/64)  // 12 k-tiles for projections (BK=64)
#define NTT (NS/64)   // 32 key tiles for attention
#define LOG2E 1.4426950408889634f

// scratch (device globals: no allocations allowed). All fp16.
// g_Q is pre-scaled by log2e/64: scores come out in log2 domain so softmax
// numerator is ex2(score). (Reference divides scores by d_k, not sqrt.)
__device__ __half g_Q[NB*NH*NS*NDK];
__device__ __half g_K[NB*NH*NS*NDK];
__device__ __half g_V[NB*NH*NS*NDK];
__device__ __half g_att[NM*ND];
__device__ __half g_xh[NM*ND];
__device__ __half g_Wqh[ND*ND];
__device__ __half g_Wkh[ND*ND];
__device__ __half g_Wvh[ND*ND];
__device__ __half g_Woh[ND*ND];

// ---------------------------------------------------------------------------
// helpers
// ---------------------------------------------------------------------------
__device__ __forceinline__ uint32_t smem_u32(const void* p){
    uint32_t a;
    asm("{ .reg .u64 t; cvta.to.shared.u64 t, %1; cvt.u32.u64 %0, t; }" : "=r"(a) : "l"(p));
    return a;
}
__device__ __forceinline__ void ldm_x4(uint32_t r[4], uint32_t addr){
    asm("ldmatrix.sync.aligned.m8n8.x4.shared.b16 {%0,%1,%2,%3}, [%4];"
        : "=r"(r[0]), "=r"(r[1]), "=r"(r[2]), "=r"(r[3]) : "r"(addr));
}
__device__ __forceinline__ void ldm_x4t(uint32_t r[4], uint32_t addr){
    asm("ldmatrix.sync.aligned.m8n8.x4.trans.shared.b16 {%0,%1,%2,%3}, [%4];"
        : "=r"(r[0]), "=r"(r[1]), "=r"(r[2]), "=r"(r[3]) : "r"(addr));
}
__device__ __forceinline__ void mma_h(float d[4], const uint32_t a[4], const uint32_t b[2]){
    asm("mma.sync.aligned.m16n8k16.row.col.f32.f16.f16.f32 "
        "{%0,%1,%2,%3}, {%4,%5,%6,%7}, {%8,%9}, {%0,%1,%2,%3};"
        : "+f"(d[0]), "+f"(d[1]), "+f"(d[2]), "+f"(d[3])
        : "r"(a[0]), "r"(a[1]), "r"(a[2]), "r"(a[3]),
          "r"(b[0]), "r"(b[1]));
}
// pack two f32 (log2-domain scores) to half2 and take 2^x on both lanes.
__device__ __forceinline__ uint32_t exp2_h2(float lo, float hi){
    uint32_t s, p;
    asm("cvt.rn.f16x2.f32 %0, %1, %2;" : "=r"(s) : "f"(hi), "f"(lo));
    asm("ex2.approx.f16x2 %0, %1;" : "=r"(p) : "r"(s));
    return p;
}

#define CP_ASYNC16(dst, src) \
    asm volatile("cp.async.cg.shared.global [%0], [%1], 16;" :: "r"(dst), "l"(src) : "memory")
#define CP_COMMIT() asm volatile("cp.async.commit_group;" ::: "memory")
#define CP_WAIT(n)  asm volatile("cp.async.wait_group %0;" :: "n"(n) : "memory")

// ---------------------------------------------------------------------------
// fp32 -> fp16 pre-convert: x and all 4 weight matrices, one kernel.
// ---------------------------------------------------------------------------
#define X4U (NM*ND/4)
#define W4U (ND*ND/4)
#define TOTU (X4U + 4*W4U)

__global__ void cvtk(const float* __restrict__ x,
                     const float* __restrict__ Wq, const float* __restrict__ Wk,
                     const float* __restrict__ Wv, const float* __restrict__ Wo)
{
    for (int u = blockIdx.x*blockDim.x + threadIdx.x; u < TOTU; u += gridDim.x*blockDim.x){
        const float4* src; __half* dst; int off;
        if (u < X4U){ src = (const float4*)x; dst = g_xh; off = u; }
        else {
            int v = u - X4U;
            int wi = v / W4U; off = v - wi*W4U;
            src = (const float4*)(wi==0 ? Wq : wi==1 ? Wk : wi==2 ? Wv : Wo);
            dst = wi==0 ? g_Wqh : wi==1 ? g_Wkh : wi==2 ? g_Wvh : g_Woh;
        }
        float4 f = src[off];
        __half2 h0 = __floats2half2_rn(f.x, f.y);
        __half2 h1 = __floats2half2_rn(f.z, f.w);
        *(uint2*)(dst + 4*(size_t)off) = make_uint2(*(uint32_t*)&h0, *(uint32_t*)&h1);
    }
}

// ---------------------------------------------------------------------------
// Projection GEMM (fp16 mma, fp32 accum, 3-stage cp.async, BK=64,
// ONE barrier per k-tile). Block tile 128x128, 256 threads,
// 8 warps = 4(m) x 2(n), warp tile 32x64. (measured-best config, frozen)
// ---------------------------------------------------------------------------
#define PLDA 72                 // halves per row (144B), conflict-free ldmatrix
#define PABUF (128*PLDA)
#define PBBUF (128*PLDA)
#define PSTG  (PABUF + PBBUF)
#define PROJ_SMEM (3*PSTG*2)

__device__ __forceinline__ void proj_stage(const __half* __restrict__ A,
                                           const __half* __restrict__ W,
                                           uint32_t smb,
                                           int rowBase, int colBase, int kt, int s)
{
    const int tid = threadIdx.x;
    const uint32_t base = smb + (uint32_t)(s*PSTG)*2;
    #pragma unroll
    for (int i = 0; i < 4; i++){
        int c = tid + i*256;
        int row = c >> 3, col = (c & 7) * 8;
        CP_ASYNC16(base + (uint32_t)(row*PLDA + col)*2,
                   A + (size_t)(rowBase + row)*ND + kt*64 + col);
        CP_ASYNC16(base + (uint32_t)(PABUF + row*PLDA + col)*2,
                   W + (size_t)(colBase + row)*ND + kt*64 + col);
    }
    CP_COMMIT();
}

__device__ __forceinline__ void proj_pipeline(const __half* __restrict__ A,
                                              const __half* __restrict__ W,
                                              __half* sm,
                                              int rowBase, int colBase,
                                              float acc[2][8][4])
{
    const int lane = threadIdx.x & 31, wid = threadIdx.x >> 5;
    const int wm = wid >> 1, wn = wid & 1;
    const uint32_t smb = smem_u32(sm);

    #pragma unroll
    for (int mt = 0; mt < 2; mt++)
        #pragma unroll
        for (int nt = 0; nt < 8; nt++)
            #pragma unroll
            for (int c = 0; c < 4; c++) acc[mt][nt][c] = 0.0f;

    proj_stage(A, W, smb, rowBase, colBase, 0, 0);
    proj_stage(A, W, smb, rowBase, colBase, 1, 1);

    for (int kt = 0; kt < PNKT; kt++){
        if (kt + 1 < PNKT) CP_WAIT(1); else CP_WAIT(0);
        __syncthreads();
        if (kt + 2 < PNKT)
            proj_stage(A, W, smb, rowBase, colBase, kt+2, (kt+2)%3);

        const uint32_t base = smb + (uint32_t)((kt%3)*PSTG)*2;
        #pragma unroll
        for (int ks = 0; ks < 4; ks++){
            uint32_t a[2][4];
            #pragma unroll
            for (int mt = 0; mt < 2; mt++){
                uint32_t ad = base + (uint32_t)((wm*32 + mt*16 + (lane & 15))*PLDA
                              + ks*16 + ((lane >> 4) << 3)) * 2;
                ldm_x4(a[mt], ad);
            }
            #pragma unroll
            for (int g = 0; g < 4; g++){
                uint32_t b[4];
                uint32_t bd = base + (uint32_t)(PABUF
                              + (wn*64 + g*16 + ((lane & 16) >> 1) + (lane & 7))*PLDA
                              + ks*16 + (lane & 8)) * 2;
                ldm_x4(b, bd);
                #pragma unroll
                for (int mt = 0; mt < 2; mt++){
                    mma_h(acc[mt][2*g    ], a[mt], &b[0]);
                    mma_h(acc[mt][2*g + 1], a[mt], &b[2]);
                }
            }
        }
    }
}

// QKV projection: z selects weight/bias/output; out = half head layout.
__global__ __launch_bounds__(256, 2)
void proj_qkv(const float* __restrict__ bq, const float* __restrict__ bk,
              const float* __restrict__ bv)
{
    extern __shared__ __half psm[];

    const int z = blockIdx.z;
    const __half* W = (z == 0) ? g_Wqh : (z == 1) ? g_Wkh : g_Wvh;
    __half* out     = (z == 0) ? g_Q   : (z == 1) ? g_K   : g_V;
    const float* bias = (z == 0) ? bq : (z == 1) ? bk : bv;
    const float scale = (z == 0) ? (LOG2E/64.0f) : 1.0f;

    const int rowBase = blockIdx.x * 128;
    const int colBase = blockIdx.y * 128;
    const int lane = threadIdx.x & 31, wid = threadIdx.x >> 5;
    const int gi = lane >> 2, q = lane & 3;
    const int wm = wid >> 1, wn = wid & 1;

    float acc[2][8][4];
    proj_pipeline(g_xh, W, psm, rowBase, colBase, acc);

    #pragma unroll
    for (int mt = 0; mt < 2; mt++){
        #pragma unroll
        for (int nt = 0; nt < 8; nt++){
            int n = colBase + wn*64 + nt*8 + 2*q;
            int h = n >> 6, d = n & 63;
            float b0 = bias[n];
            float b1 = bias[n + 1];
            #pragma unroll
            for (int dr = 0; dr < 2; dr++){
                int m = rowBase + wm*32 + mt*16 + gi + dr*8;
                float v0 = (acc[mt][nt][dr*2+0] + b0) * scale;
                float v1 = (acc[mt][nt][dr*2+1] + b1) * scale;
                int bb = m >> 11, s = m & (NS-1);
                *(__half2*)&out[((size_t)(bb*NH + h)*NS + s)*NDK + d] =
                    __floats2half2_rn(v0, v1);
            }
        }
    }
}

// Output projection: A = g_att (half), W = g_Woh, float output.
__global__ __launch_bounds__(256, 2)
void proj_out(const float* __restrict__ bo, float* __restrict__ out)
{
    extern __shared__ __half psm[];

    const int rowBase = blockIdx.x * 128;
    const int colBase = blockIdx.y * 128;
    const int lane = threadIdx.x & 31, wid = threadIdx.x >> 5;
    const int gi = lane >> 2, q = lane & 3;
    const int wm = wid >> 1, wn = wid & 1;

    float acc[2][8][4];
    proj_pipeline(g_att, g_Woh, psm, rowBase, colBase, acc);

    #pragma unroll
    for (int mt = 0; mt < 2; mt++){
        #pragma unroll
        for (int nt = 0; nt < 8; nt++){
            int n = colBase + wn*64 + nt*8 + 2*q;
            float b0 = bo[n];
            float b1 = bo[n + 1];
            #pragma unroll
            for (int dr = 0; dr < 2; dr++){
                int m = rowBase + wm*32 + mt*16 + gi + dr*8;
                *(float2*)&out[(size_t)m*ND + n] =
                    make_float2(acc[mt][nt][dr*2+0] + b0, acc[mt][nt][dr*2+1] + b1);
            }
        }
    }
}

// ---------------------------------------------------------------------------
// Flash attention (fp16 mma, fp32 accum). NEW: 256-thread CTA (8 warps)
// over a 128-row q-tile, warp = 16 q-rows x all 64 keys, 2-stage cp.async,
// 2 CTAs/SM -> 16 warps/SM with the LOW K/V L2 traffic of 128-row tiles
// (393MB, vs 786MB for the 64-row variant). Scores in log2 domain;
// P = ex2.f16x2; Q fragments register-resident; l-sum via constant ones
// B-fragment. smem 54KB/CTA.
// ---------------------------------------------------------------------------
#define ALD 72   // halves per row (144B): conflict-free ldmatrix stride
#define AKBUF (64*ALD)
#define ATT_SMEM ((128*ALD + 4*AKBUF)*2)   // Q(128 rows) + 2x(K,V) = 55296 B

__device__ __forceinline__ void attn_stage(const __half* __restrict__ Kg,
                                           const __half* __restrict__ Vg,
                                           uint32_t ksb, uint32_t vsb,
                                           int kt, int s)
{
    const int tid = threadIdx.x;
    #pragma unroll
    for (int i = 0; i < 2; i++){
        int fid = tid + i*256;
        int row = fid >> 3, col = (fid & 7) * 8;
        CP_ASYNC16(ksb + (uint32_t)(s*AKBUF + row*ALD + col)*2,
                   Kg + (size_t)(kt*64 + row)*NDK + col);
        CP_ASYNC16(vsb + (uint32_t)(s*AKBUF + row*ALD + col)*2,
                   Vg + (size_t)(kt*64 + row)*NDK + col);
    }
    CP_COMMIT();
}

__global__ __launch_bounds__(256, 2)
void attn_h()
{
    extern __shared__ __half dsm[];
    __half* Qs = dsm;                 // [128][ALD]
    __half* Ks = Qs + 128*ALD;        // [2][64][ALD]
    __half* Vs = Ks + 2*AKBUF;        // [2][64][ALD]

    const int tid  = threadIdx.x;
    const int lane = tid & 31, wid = tid >> 5;
    const int gi = lane >> 2, q = lane & 3;
    const int qt = blockIdx.x, bh = blockIdx.y;

    const __half* Qg = g_Q + ((size_t)bh*NS + qt*128)*NDK;
    const __half* Kg = g_K + (size_t)bh*NS*NDK;
    const __half* Vg = g_V + (size_t)bh*NS*NDK;

    const uint32_t qsb = smem_u32(Qs), ksb = smem_u32(Ks), vsb = smem_u32(Vs);

    // prologue: Q (128 rows x 64 halves) folded into the stage-0 commit group
    #pragma unroll
    for (int i = 0; i < 4; i++){
        int fid = tid + i*256;
        int row = fid >> 3, col = (fid & 7) * 8;
        CP_ASYNC16(qsb + (uint32_t)(row*ALD + col)*2,
                   Qg + (size_t)row*NDK + col);
    }
    attn_stage(Kg, Vg, ksb, vsb, 0, 0);

    float o[8][4];     // O accumulators (16 rows x 64 cols per warp)
    float o1[4];       // ones-column accumulators (l sums)
    #pragma unroll
    for (int nt = 0; nt < 8; nt++)
        #pragma unroll
        for (int c = 0; c < 4; c++) o[nt][c] = 0.0f;
    #pragma unroll
    for (int c = 0; c < 4; c++) o1[c] = 0.0f;

    const int r0 = wid * 16;

    // constant ones-column B fragment (n8k16): col 0 of the tile is 1.0 for
    // every k -> lanes with gi==0 hold {1.0h,1.0h} in both regs, others 0.
    const uint32_t bOne[2] = { (gi == 0) ? 0x3C003C00u : 0u,
                               (gi == 0) ? 0x3C003C00u : 0u };

    // Q is tile-invariant: wait for stage 0 (includes Q), hoist Q fragments.
    CP_WAIT(0);
    __syncthreads();
    uint32_t qa[4][4];   // [ks][4]
    #pragma unroll
    for (int ks = 0; ks < 4; ks++){
        uint32_t ad = qsb + (uint32_t)((r0 + (lane & 15))*ALD
                      + ks*16 + ((lane >> 4) << 3)) * 2;
        ldm_x4(qa[ks], ad);
    }
    // prefetch stage 1 now that stage-0 wait is done
    attn_stage(Kg, Vg, ksb, vsb, 1, 1);

    for (int kt = 0; kt < NTT; kt++){
        if (kt > 0){
            CP_WAIT(0);            // stage kt resident
            __syncthreads();       // all warps done reading buffer (kt+1)&1
            if (kt + 1 < NTT)
                attn_stage(Kg, Vg, ksb, vsb, kt+1, (kt+1)&1);
        }

        const uint32_t kbase = ksb + (uint32_t)((kt&1)*AKBUF)*2;
        const uint32_t vbase = vsb + (uint32_t)((kt&1)*AKBUF)*2;

        // ---- S = Q . K^T : 16 rows x 64 keys per warp (log2 domain) ----
        float sc[8][4];
        #pragma unroll
        for (int nt = 0; nt < 8; nt++)
            #pragma unroll
            for (int c = 0; c < 4; c++) sc[nt][c] = 0.0f;

        #pragma unroll
        for (int ks = 0; ks < 4; ks++){
            #pragma unroll
            for (int g = 0; g < 4; g++){
                uint32_t b[4];
                uint32_t bd = kbase + (uint32_t)((g*16 + ((lane & 16) >> 1)
                              + (lane & 7))*ALD + ks*16 + (lane & 8)) * 2;
                ldm_x4(b, bd);
                mma_h(sc[2*g    ], qa[ks], &b[0]);
                mma_h(sc[2*g + 1], qa[ks], &b[2]);
            }
        }

        // ---- P = 2^S, packed straight into half2 A-fragments ----
        uint32_t P[8][2];
        #pragma unroll
        for (int nt = 0; nt < 8; nt++){
            P[nt][0] = exp2_h2(sc[nt][0], sc[nt][1]);
            P[nt][1] = exp2_h2(sc[nt][2], sc[nt][3]);
        }

        // ---- O += P . V  (+ constant ones tile accumulating l) ----
        #pragma unroll
        for (int ks2 = 0; ks2 < 4; ks2++){
            uint32_t a2[4] = { P[2*ks2][0], P[2*ks2][1],
                               P[2*ks2+1][0], P[2*ks2+1][1] };
            #pragma unroll
            for (int g = 0; g < 4; g++){
                uint32_t b[4];
                uint32_t vd = vbase + (uint32_t)((ks2*16 + (lane & 8)
                              + (lane & 7))*ALD + g*16 + ((lane & 16) >> 1)) * 2;
                ldm_x4t(b, vd);
                mma_h(o[2*g    ], a2, &b[0]);
                mma_h(o[2*g + 1], a2, &b[2]);
            }
            mma_h(o1, a2, bOne);
        }
    }

    // ---- l lives in o1 at q=0 (col 0 of the ones tile): broadcast ----
    const int bb = bh / NH, h = bh % NH;
    {
        float l0 = __shfl_sync(0xffffffffu, o1[0], lane & 28);
        float l1 = __shfl_sync(0xffffffffu, o1[2], lane & 28);
        float inv0 = 1.0f / l0;
        float inv1 = 1.0f / l1;
        int row = qt*128 + r0 + gi;
        #pragma unroll
        for (int nt = 0; nt < 8; nt++){
            int d = nt*8 + 2*q;
            *(__half2*)&g_att[((size_t)(bb*NS + row    ))*ND + h*NDK + d] =
                __floats2half2_rn(o[nt][0]*inv0, o[nt][1]*inv0);
            *(__half2*)&g_att[((size_t)(bb*NS + row + 8))*ND + h*NDK + d] =
                __floats2half2_rn(o[nt][2]*inv1, o[nt][3]*inv1);
        }
    }
}

// ---------------------------------------------------------------------------
extern "C" void kernel_launch(void* const* d_in, const int* in_sizes, int n_in,
                              void* d_out, int out_size)
{
    (void)in_sizes; (void)n_in; (void)out_size;
    const float* x  = (const float*)d_in[0];
    const float* Wq = (const float*)d_in[1];
    const float* bq = (const float*)d_in[2];
    const float* Wk = (const float*)d_in[3];
    const float* bk = (const float*)d_in[4];
    const float* Wv = (const float*)d_in[5];
    const float* bv = (const float*)d_in[6];
    const float* Wo = (const float*)d_in[7];
    const float* bo = (const float*)d_in[8];

    cudaFuncSetAttribute(attn_h,
                         cudaFuncAttributeMaxDynamicSharedMemorySize, ATT_SMEM);
    cudaFuncSetAttribute(proj_qkv,
                         cudaFuncAttributeMaxDynamicSharedMemorySize, PROJ_SMEM);
    cudaFuncSetAttribute(proj_out,
                         cudaFuncAttributeMaxDynamicSharedMemorySize, PROJ_SMEM);

    cvtk<<<2048, 256>>>(x, Wq, Wk, Wv, Wo);
    proj_qkv<<<dim3(NM/128, ND/128, 3), 256, PROJ_SMEM>>>(bq, bk, bv);
    attn_h<<<dim3(NS/128, NB*NH), 256, ATT_SMEM>>>();
    proj_out<<<dim3(NM/128, ND/128), 256, PROJ_SMEM>>>(bo, (float*)d_out);
}

// round 17
// speedup vs baseline: 1.0537x; 1.0537x over previous
#include <cuda_runtime.h>
#include <cuda_fp16.h>
#include <math.h>
#include <cstdint>

#define NB 4
#define NS 2048
#define ND 768
#define NH 12
#define NDK 64
#define NM (NB*NS)
#define PNKT (ND/64)  // 12 k-tiles for projections (BK=64)
#define NTT (NS/64)   // 32 key tiles for attention
#define NQT (NS/64)   // 32 q-tiles (64 rows each)
#define NITEM (NQT*NB*NH)   // 1536 attention work items
#define NPERS 592           // persistent CTAs: 4/SM x 148 SMs
#define LOG2E 1.4426950408889634f

// scratch (device globals: no allocations allowed). All fp16.
// g_Q is pre-scaled by log2e/64: scores come out in log2 domain so softmax
// numerator is ex2(score). (Reference divides scores by d_k, not sqrt.)
__device__ __half g_Q[NB*NH*NS*NDK];
__device__ __half g_K[NB*NH*NS*NDK];
__device__ __half g_V[NB*NH*NS*NDK];
__device__ __half g_att[NM*ND];
__device__ __half g_xh[NM*ND];
__device__ __half g_Wqh[ND*ND];
__device__ __half g_Wkh[ND*ND];
__device__ __half g_Wvh[ND*ND];
__device__ __half g_Woh[ND*ND];

// ---------------------------------------------------------------------------
// helpers
// ---------------------------------------------------------------------------
__device__ __forceinline__ uint32_t smem_u32(const void* p){
    uint32_t a;
    asm("{ .reg .u64 t; cvta.to.shared.u64 t, %1; cvt.u32.u64 %0, t; }" : "=r"(a) : "l"(p));
    return a;
}
__device__ __forceinline__ void ldm_x4(uint32_t r[4], uint32_t addr){
    asm("ldmatrix.sync.aligned.m8n8.x4.shared.b16 {%0,%1,%2,%3}, [%4];"
        : "=r"(r[0]), "=r"(r[1]), "=r"(r[2]), "=r"(r[3]) : "r"(addr));
}
__device__ __forceinline__ void ldm_x4t(uint32_t r[4], uint32_t addr){
    asm("ldmatrix.sync.aligned.m8n8.x4.trans.shared.b16 {%0,%1,%2,%3}, [%4];"
        : "=r"(r[0]), "=r"(r[1]), "=r"(r[2]), "=r"(r[3]) : "r"(addr));
}
__device__ __forceinline__ void mma_h(float d[4], const uint32_t a[4], const uint32_t b[2]){
    asm("mma.sync.aligned.m16n8k16.row.col.f32.f16.f16.f32 "
        "{%0,%1,%2,%3}, {%4,%5,%6,%7}, {%8,%9}, {%0,%1,%2,%3};"
        : "+f"(d[0]), "+f"(d[1]), "+f"(d[2]), "+f"(d[3])
        : "r"(a[0]), "r"(a[1]), "r"(a[2]), "r"(a[3]),
          "r"(b[0]), "r"(b[1]));
}
// pack two f32 (log2-domain scores) to half2 and take 2^x on both lanes.
__device__ __forceinline__ uint32_t exp2_h2(float lo, float hi){
    uint32_t s, p;
    asm("cvt.rn.f16x2.f32 %0, %1, %2;" : "=r"(s) : "f"(hi), "f"(lo));
    asm("ex2.approx.f16x2 %0, %1;" : "=r"(p) : "r"(s));
    return p;
}

#define CP_ASYNC16(dst, src) \
    asm volatile("cp.async.cg.shared.global [%0], [%1], 16;" :: "r"(dst), "l"(src) : "memory")
#define CP_COMMIT() asm volatile("cp.async.commit_group;" ::: "memory")
#define CP_WAIT(n)  asm volatile("cp.async.wait_group %0;" :: "n"(n) : "memory")

// ---------------------------------------------------------------------------
// fp32 -> fp16 pre-convert: x and all 4 weight matrices, one kernel.
// ---------------------------------------------------------------------------
#define X4U (NM*ND/4)
#define W4U (ND*ND/4)
#define TOTU (X4U + 4*W4U)

__global__ void cvtk(const float* __restrict__ x,
                     const float* __restrict__ Wq, const float* __restrict__ Wk,
                     const float* __restrict__ Wv, const float* __restrict__ Wo)
{
    for (int u = blockIdx.x*blockDim.x + threadIdx.x; u < TOTU; u += gridDim.x*blockDim.x){
        const float4* src; __half* dst; int off;
        if (u < X4U){ src = (const float4*)x; dst = g_xh; off = u; }
        else {
            int v = u - X4U;
            int wi = v / W4U; off = v - wi*W4U;
            src = (const float4*)(wi==0 ? Wq : wi==1 ? Wk : wi==2 ? Wv : Wo);
            dst = wi==0 ? g_Wqh : wi==1 ? g_Wkh : wi==2 ? g_Wvh : g_Woh;
        }
        float4 f = src[off];
        __half2 h0 = __floats2half2_rn(f.x, f.y);
        __half2 h1 = __floats2half2_rn(f.z, f.w);
        *(uint2*)(dst + 4*(size_t)off) = make_uint2(*(uint32_t*)&h0, *(uint32_t*)&h1);
    }
}

// ---------------------------------------------------------------------------
// Projection GEMM (fp16 mma, fp32 accum, 3-stage cp.async, BK=64,
// ONE barrier per k-tile). Block tile 128x128, 256 threads,
// 8 warps = 4(m) x 2(n), warp tile 32x64. (measured-best config, frozen)
// ---------------------------------------------------------------------------
#define PLDA 72                 // halves per row (144B), conflict-free ldmatrix
#define PABUF (128*PLDA)
#define PBBUF (128*PLDA)
#define PSTG  (PABUF + PBBUF)
#define PROJ_SMEM (3*PSTG*2)

__device__ __forceinline__ void proj_stage(const __half* __restrict__ A,
                                           const __half* __restrict__ W,
                                           uint32_t smb,
                                           int rowBase, int colBase, int kt, int s)
{
    const int tid = threadIdx.x;
    const uint32_t base = smb + (uint32_t)(s*PSTG)*2;
    #pragma unroll
    for (int i = 0; i < 4; i++){
        int c = tid + i*256;
        int row = c >> 3, col = (c & 7) * 8;
        CP_ASYNC16(base + (uint32_t)(row*PLDA + col)*2,
                   A + (size_t)(rowBase + row)*ND + kt*64 + col);
        CP_ASYNC16(base + (uint32_t)(PABUF + row*PLDA + col)*2,
                   W + (size_t)(colBase + row)*ND + kt*64 + col);
    }
    CP_COMMIT();
}

__device__ __forceinline__ void proj_pipeline(const __half* __restrict__ A,
                                              const __half* __restrict__ W,
                                              __half* sm,
                                              int rowBase, int colBase,
                                              float acc[2][8][4])
{
    const int lane = threadIdx.x & 31, wid = threadIdx.x >> 5;
    const int wm = wid >> 1, wn = wid & 1;
    const uint32_t smb = smem_u32(sm);

    #pragma unroll
    for (int mt = 0; mt < 2; mt++)
        #pragma unroll
        for (int nt = 0; nt < 8; nt++)
            #pragma unroll
            for (int c = 0; c < 4; c++) acc[mt][nt][c] = 0.0f;

    proj_stage(A, W, smb, rowBase, colBase, 0, 0);
    proj_stage(A, W, smb, rowBase, colBase, 1, 1);

    for (int kt = 0; kt < PNKT; kt++){
        if (kt + 1 < PNKT) CP_WAIT(1); else CP_WAIT(0);
        __syncthreads();
        if (kt + 2 < PNKT)
            proj_stage(A, W, smb, rowBase, colBase, kt+2, (kt+2)%3);

        const uint32_t base = smb + (uint32_t)((kt%3)*PSTG)*2;
        #pragma unroll
        for (int ks = 0; ks < 4; ks++){
            uint32_t a[2][4];
            #pragma unroll
            for (int mt = 0; mt < 2; mt++){
                uint32_t ad = base + (uint32_t)((wm*32 + mt*16 + (lane & 15))*PLDA
                              + ks*16 + ((lane >> 4) << 3)) * 2;
                ldm_x4(a[mt], ad);
            }
            #pragma unroll
            for (int g = 0; g < 4; g++){
                uint32_t b[4];
                uint32_t bd = base + (uint32_t)(PABUF
                              + (wn*64 + g*16 + ((lane & 16) >> 1) + (lane & 7))*PLDA
                              + ks*16 + (lane & 8)) * 2;
                ldm_x4(b, bd);
                #pragma unroll
                for (int mt = 0; mt < 2; mt++){
                    mma_h(acc[mt][2*g    ], a[mt], &b[0]);
                    mma_h(acc[mt][2*g + 1], a[mt], &b[2]);
                }
            }
        }
    }
}

// QKV projection: z selects weight/bias/output; out = half head layout.
__global__ __launch_bounds__(256, 2)
void proj_qkv(const float* __restrict__ bq, const float* __restrict__ bk,
              const float* __restrict__ bv)
{
    extern __shared__ __half psm[];

    const int z = blockIdx.z;
    const __half* W = (z == 0) ? g_Wqh : (z == 1) ? g_Wkh : g_Wvh;
    __half* out     = (z == 0) ? g_Q   : (z == 1) ? g_K   : g_V;
    const float* bias = (z == 0) ? bq : (z == 1) ? bk : bv;
    const float scale = (z == 0) ? (LOG2E/64.0f) : 1.0f;

    const int rowBase = blockIdx.x * 128;
    const int colBase = blockIdx.y * 128;
    const int lane = threadIdx.x & 31, wid = threadIdx.x >> 5;
    const int gi = lane >> 2, q = lane & 3;
    const int wm = wid >> 1, wn = wid & 1;

    float acc[2][8][4];
    proj_pipeline(g_xh, W, psm, rowBase, colBase, acc);

    #pragma unroll
    for (int mt = 0; mt < 2; mt++){
        #pragma unroll
        for (int nt = 0; nt < 8; nt++){
            int n = colBase + wn*64 + nt*8 + 2*q;
            int h = n >> 6, d = n & 63;
            float b0 = bias[n];
            float b1 = bias[n + 1];
            #pragma unroll
            for (int dr = 0; dr < 2; dr++){
                int m = rowBase + wm*32 + mt*16 + gi + dr*8;
                float v0 = (acc[mt][nt][dr*2+0] + b0) * scale;
                float v1 = (acc[mt][nt][dr*2+1] + b1) * scale;
                int bb = m >> 11, s = m & (NS-1);
                *(__half2*)&out[((size_t)(bb*NH + h)*NS + s)*NDK + d] =
                    __floats2half2_rn(v0, v1);
            }
        }
    }
}

// Output projection: A = g_att (half), W = g_Woh, float output.
__global__ __launch_bounds__(256, 2)
void proj_out(const float* __restrict__ bo, float* __restrict__ out)
{
    extern __shared__ __half psm[];

    const int rowBase = blockIdx.x * 128;
    const int colBase = blockIdx.y * 128;
    const int lane = threadIdx.x & 31, wid = threadIdx.x >> 5;
    const int gi = lane >> 2, q = lane & 3;
    const int wm = wid >> 1, wn = wid & 1;

    float acc[2][8][4];
    proj_pipeline(g_att, g_Woh, psm, rowBase, colBase, acc);

    #pragma unroll
    for (int mt = 0; mt < 2; mt++){
        #pragma unroll
        for (int nt = 0; nt < 8; nt++){
            int n = colBase + wn*64 + nt*8 + 2*q;
            float b0 = bo[n];
            float b1 = bo[n + 1];
            #pragma unroll
            for (int dr = 0; dr < 2; dr++){
                int m = rowBase + wm*32 + mt*16 + gi + dr*8;
                *(float2*)&out[(size_t)m*ND + n] =
                    make_float2(acc[mt][nt][dr*2+0] + b0, acc[mt][nt][dr*2+1] + b1);
            }
        }
    }
}

// ---------------------------------------------------------------------------
// Flash attention (fp16 mma, fp32 accum), PERSISTENT version of the round-15
// config (measured best): 64-row q-tiles, 2-stage cp.async K/V, 4 CTAs/SM,
// CTA = 128 threads (4 warps), warp = 16 q-rows x all 64 keys. Exactly
// NPERS=592 CTAs; each loops over work items (qt,bh), removing the 2.59-wave
// quantization tail. Scores in log2 domain; P = ex2.f16x2; Q fragments
// register-resident per item; l-sum via constant ones B-fragment.
// Inter-item safety: the CP_WAIT(0)+__syncthreads before each item's Q-hoist
// gates buffer reuse behind all warps completing the previous item.
// ---------------------------------------------------------------------------
#define ALD 72   // halves per row (144B): conflict-free ldmatrix stride
#define AKBUF (64*ALD)
#define ATT_SMEM ((64*ALD + 4*AKBUF)*2)   // Q(64 rows) + 2x(K,V) = 46080 B

__device__ __forceinline__ void attn_stage(const __half* __restrict__ Kg,
                                           const __half* __restrict__ Vg,
                                           uint32_t ksb, uint32_t vsb,
                                           int kt, int s)
{
    const int tid = threadIdx.x;
    #pragma unroll
    for (int i = 0; i < 4; i++){
        int fid = tid + i*128;
        int row = fid >> 3, col = (fid & 7) * 8;
        CP_ASYNC16(ksb + (uint32_t)(s*AKBUF + row*ALD + col)*2,
                   Kg + (size_t)(kt*64 + row)*NDK + col);
        CP_ASYNC16(vsb + (uint32_t)(s*AKBUF + row*ALD + col)*2,
                   Vg + (size_t)(kt*64 + row)*NDK + col);
    }
    CP_COMMIT();
}

__global__ __launch_bounds__(128, 4)
void attn_h()
{
    extern __shared__ __half dsm[];
    __half* Qs = dsm;                 // [64][ALD]
    __half* Ks = Qs + 64*ALD;         // [2][64][ALD]
    __half* Vs = Ks + 2*AKBUF;        // [2][64][ALD]

    const int tid  = threadIdx.x;
    const int lane = tid & 31, wid = tid >> 5;
    const int gi = lane >> 2, q = lane & 3;

    const uint32_t qsb = smem_u32(Qs), ksb = smem_u32(Ks), vsb = smem_u32(Vs);
    const int r0 = wid * 16;

    // constant ones-column B fragment (n8k16): col 0 of the tile is 1.0 for
    // every k -> lanes with gi==0 hold {1.0h,1.0h} in both regs, others 0.
    const uint32_t bOne[2] = { (gi == 0) ? 0x3C003C00u : 0u,
                               (gi == 0) ? 0x3C003C00u : 0u };

    for (int w = blockIdx.x; w < NITEM; w += NPERS){
        const int qt = w & (NQT - 1);
        const int bh = w >> 5;           // NQT == 32

        const __half* Qg = g_Q + ((size_t)bh*NS + qt*64)*NDK;
        const __half* Kg = g_K + (size_t)bh*NS*NDK;
        const __half* Vg = g_V + (size_t)bh*NS*NDK;

        // prologue: Q (64 rows x 64 halves) folded into the stage-0 group
        {
            int row = tid >> 1, cb = (tid & 1) * 32;
            #pragma unroll
            for (int i = 0; i < 4; i++)
                CP_ASYNC16(qsb + (uint32_t)(row*ALD + cb + i*8)*2,
                           Qg + (size_t)row*NDK + cb + i*8);
        }
        attn_stage(Kg, Vg, ksb, vsb, 0, 0);

        float o[8][4];     // O accumulators (16 rows x 64 cols per warp)
        float o1[4];       // ones-column accumulators (l sums)
        #pragma unroll
        for (int nt = 0; nt < 8; nt++)
            #pragma unroll
            for (int c = 0; c < 4; c++) o[nt][c] = 0.0f;
        #pragma unroll
        for (int c = 0; c < 4; c++) o1[c] = 0.0f;

        // wait for stage 0 (includes Q); this sync also gates smem reuse
        // against laggard warps of the previous item.
        CP_WAIT(0);
        __syncthreads();
        uint32_t qa[4][4];   // [ks][4]
        #pragma unroll
        for (int ks = 0; ks < 4; ks++){
            uint32_t ad = qsb + (uint32_t)((r0 + (lane & 15))*ALD
                          + ks*16 + ((lane >> 4) << 3)) * 2;
            ldm_x4(qa[ks], ad);
        }
        attn_stage(Kg, Vg, ksb, vsb, 1, 1);

        for (int kt = 0; kt < NTT; kt++){
            if (kt > 0){
                CP_WAIT(0);            // stage kt resident
                __syncthreads();       // all warps done reading buffer (kt+1)&1
                if (kt + 1 < NTT)
                    attn_stage(Kg, Vg, ksb, vsb, kt+1, (kt+1)&1);
            }

            const uint32_t kbase = ksb + (uint32_t)((kt&1)*AKBUF)*2;
            const uint32_t vbase = vsb + (uint32_t)((kt&1)*AKBUF)*2;

            // ---- S = Q . K^T : 16 rows x 64 keys per warp (log2 domain) ----
            float sc[8][4];
            #pragma unroll
            for (int nt = 0; nt < 8; nt++)
                #pragma unroll
                for (int c = 0; c < 4; c++) sc[nt][c] = 0.0f;

            #pragma unroll
            for (int ks = 0; ks < 4; ks++){
                #pragma unroll
                for (int g = 0; g < 4; g++){
                    uint32_t b[4];
                    uint32_t bd = kbase + (uint32_t)((g*16 + ((lane & 16) >> 1)
                                  + (lane & 7))*ALD + ks*16 + (lane & 8)) * 2;
                    ldm_x4(b, bd);
                    mma_h(sc[2*g    ], qa[ks], &b[0]);
                    mma_h(sc[2*g + 1], qa[ks], &b[2]);
                }
            }

            // ---- P = 2^S, packed straight into half2 A-fragments ----
            uint32_t P[8][2];
            #pragma unroll
            for (int nt = 0; nt < 8; nt++){
                P[nt][0] = exp2_h2(sc[nt][0], sc[nt][1]);
                P[nt][1] = exp2_h2(sc[nt][2], sc[nt][3]);
            }

            // ---- O += P . V  (+ constant ones tile accumulating l) ----
            #pragma unroll
            for (int ks2 = 0; ks2 < 4; ks2++){
                uint32_t a2[4] = { P[2*ks2][0], P[2*ks2][1],
                                   P[2*ks2+1][0], P[2*ks2+1][1] };
                #pragma unroll
                for (int g = 0; g < 4; g++){
                    uint32_t b[4];
                    uint32_t vd = vbase + (uint32_t)((ks2*16 + (lane & 8)
                                  + (lane & 7))*ALD + g*16 + ((lane & 16) >> 1)) * 2;
                    ldm_x4t(b, vd);
                    mma_h(o[2*g    ], a2, &b[0]);
                    mma_h(o[2*g + 1], a2, &b[2]);
                }
                mma_h(o1, a2, bOne);
            }
        }

        // ---- epilogue: l from ones column (q==0 lanes), normalize, write ----
        const int bb = bh / NH, h = bh % NH;
        {
            float l0 = __shfl_sync(0xffffffffu, o1[0], lane & 28);
            float l1 = __shfl_sync(0xffffffffu, o1[2], lane & 28);
            float inv0 = 1.0f / l0;
            float inv1 = 1.0f / l1;
            int row = qt*64 + r0 + gi;
            #pragma unroll
            for (int nt = 0; nt < 8; nt++){
                int d = nt*8 + 2*q;
                *(__half2*)&g_att[((size_t)(bb*NS + row    ))*ND + h*NDK + d] =
                    __floats2half2_rn(o[nt][0]*inv0, o[nt][1]*inv0);
                *(__half2*)&g_att[((size_t)(bb*NS + row + 8))*ND + h*NDK + d] =
                    __floats2half2_rn(o[nt][2]*inv1, o[nt][3]*inv1);
            }
        }
    }
}

// ---------------------------------------------------------------------------
extern "C" void kernel_launch(void* const* d_in, const int* in_sizes, int n_in,
                              void* d_out, int out_size)
{
    (void)in_sizes; (void)n_in; (void)out_size;
    const float* x  = (const float*)d_in[0];
    const float* Wq = (const float*)d_in[1];
    const float* bq = (const float*)d_in[2];
    const float* Wk = (const float*)d_in[3];
    const float* bk = (const float*)d_in[4];
    const float* Wv = (const float*)d_in[5];
    const float* bv = (const float*)d_in[6];
    const float* Wo = (const float*)d_in[7];
    const float* bo = (const float*)d_in[8];

    cudaFuncSetAttribute(attn_h,
                         cudaFuncAttributeMaxDynamicSharedMemorySize, ATT_SMEM);
    cudaFuncSetAttribute(proj_qkv,
                         cudaFuncAttributeMaxDynamicSharedMemorySize, PROJ_SMEM);
    cudaFuncSetAttribute(proj_out,
                         cudaFuncAttributeMaxDynamicSharedMemorySize, PROJ_SMEM);

    cvtk<<<2048, 256>>>(x, Wq, Wk, Wv, Wo);
    proj_qkv<<<dim3(NM/128, ND/128, 3), 256, PROJ_SMEM>>>(bq, bk, bv);
    attn_h<<<NPERS, 128, ATT_SMEM>>>();
    proj_out<<<dim3(NM/128, ND/128), 256, PROJ_SMEM>>>(bo, (float*)d_out);
}